// round 17
// baseline (speedup 1.0000x reference)
#include <cuda_runtime.h>
#include <cuda_fp16.h>
#include <math.h>
#include <stdint.h>

// Problem constants: B=8, N=4096, C=512, HEAD=8, d=64, SR=2, H=W=64, M=1024

// -------------------- scratch (device globals) -------------------------------
__device__ __half g_ctxh[32768 * 512];
__device__ __half g_wf_h[1024 * 2048];
__device__ float  g_b2[1024];
__device__ __half g_xh[32768 * 512];
__device__ __half g_wqh[512 * 512];
__device__ __half g_wkh[512 * 512];     // Wk ⊙ gk (fp16)
__device__ __half g_wvh[512 * 512];     // Wv ⊙ gv (fp16)
__device__ __half g_wph[512 * 512];
__device__ __half g_srkv_h[8192 * 1024];   // raw conv out (pre-LN)
__device__ float  g_stats[2 * 8192 * 2];   // [half][row][sum,sumsq]
__device__ float  g_sk[512], g_tk[512], g_sv[512], g_tv[512];
__device__ __half g_qh[32768 * 512];
__device__ __half g_kh[8192 * 512];
__device__ __half g_vh[8192 * 512];
__device__ __half g_atth[32768 * 512];

// -------------------- helpers ------------------------------------------------
__device__ __forceinline__ uint32_t h2(float a, float b) {
    uint32_t r;
    asm("cvt.rn.f16x2.f32 %0, %2, %1;" : "=r"(r) : "f"(a), "f"(b));
    return r;
}
__device__ __forceinline__ float ex2f(float x) {
    float y;
    asm("ex2.approx.f32 %0, %1;" : "=f"(y) : "f"(x));
    return y;
}
__device__ __forceinline__ void mma16(float* c, const uint32_t* a,
                                      uint32_t b0, uint32_t b1) {
    asm("mma.sync.aligned.m16n8k16.row.col.f32.f16.f16.f32 "
        "{%0,%1,%2,%3},{%4,%5,%6,%7},{%8,%9},{%0,%1,%2,%3};"
        : "+f"(c[0]), "+f"(c[1]), "+f"(c[2]), "+f"(c[3])
        : "r"(a[0]), "r"(a[1]), "r"(a[2]), "r"(a[3]), "r"(b0), "r"(b1));
}
__device__ __forceinline__ uint32_t smem_u32(const void* p) {
    return (uint32_t)__cvta_generic_to_shared(p);
}
__device__ __forceinline__ void ldsm4(uint32_t* r, uint32_t addr) {
    asm volatile("ldmatrix.sync.aligned.m8n8.x4.shared.b16 {%0,%1,%2,%3}, [%4];"
                 : "=r"(r[0]), "=r"(r[1]), "=r"(r[2]), "=r"(r[3]) : "r"(addr));
}
__device__ __forceinline__ void ldsm4t(uint32_t* r, uint32_t addr) {
    asm volatile("ldmatrix.sync.aligned.m8n8.x4.trans.shared.b16 {%0,%1,%2,%3}, [%4];"
                 : "=r"(r[0]), "=r"(r[1]), "=r"(r[2]), "=r"(r[3]) : "r"(addr));
}
__device__ __forceinline__ void cpa16(uint32_t smem, const void* g) {
    asm volatile("cp.async.cg.shared.global [%0], [%1], 16;"
                 :: "r"(smem), "l"(g) : "memory");
}
#define CP_COMMIT() asm volatile("cp.async.commit_group;" ::: "memory")
#define CP_WAIT(n)  asm volatile("cp.async.wait_group %0;" :: "n"(n) : "memory")

// -------------------- mega prep (unchanged from round 16) --------------------
__global__ void mega_prep(
    const float* __restrict__ x, __half* __restrict__ xh,
    const float* __restrict__ ctx, __half* __restrict__ ctxh,
    const float* __restrict__ Wq, const float* __restrict__ Wk,
    const float* __restrict__ Wv, const float* __restrict__ Wp,
    __half* __restrict__ wqh, __half* __restrict__ wkh,
    __half* __restrict__ wvh, __half* __restrict__ wph,
    const float* __restrict__ gk, const float* __restrict__ gv,
    const float* __restrict__ Wsrk, const float* __restrict__ Wsrv,
    __half* __restrict__ wf,
    const float* __restrict__ bek, const float* __restrict__ bev,
    const float* __restrict__ bk, const float* __restrict__ bv,
    float* __restrict__ sk, float* __restrict__ tk,
    float* __restrict__ sv, float* __restrict__ tv,
    const float* __restrict__ bsrk, const float* __restrict__ bsrv,
    float* __restrict__ b2, float* __restrict__ stats)
{
    int bid = blockIdx.x, tid = threadIdx.x;
    if (bid < 32768) {
        const float* s = bid < 16384 ? x : ctx;
        __half* d = bid < 16384 ? xh : ctxh;
        int i = (bid & 16383) * 256 + tid;
        float4 v = ((const float4*)s)[i];
        ((uint2*)d)[i] = make_uint2(h2(v.x, v.y), h2(v.z, v.w));
    } else if (bid < 33792) {
        int i = (bid - 32768) * 256 + tid;
        int sel = i >> 16, off = i & 65535;
        const float* s = sel == 0 ? Wq : sel == 1 ? Wk : sel == 2 ? Wv : Wp;
        __half* d = sel == 0 ? wqh : sel == 1 ? wkh : sel == 2 ? wvh : wph;
        float4 v = ((const float4*)s)[off];
        if (sel == 1) {
            float4 gg = ((const float4*)gk)[off & 127];
            v.x *= gg.x; v.y *= gg.y; v.z *= gg.z; v.w *= gg.w;
        } else if (sel == 2) {
            float4 gg = ((const float4*)gv)[off & 127];
            v.x *= gg.x; v.y *= gg.y; v.z *= gg.z; v.w *= gg.w;
        }
        ((uint2*)d)[off] = make_uint2(h2(v.x, v.y), h2(v.z, v.w));
    } else if (bid < 41984) {
        int idx = (bid - 33792) * 256 + tid;
        int z = idx >> 20, j = idx & 1048575;
        const float* src = z ? Wsrv : Wsrk;
        __half* d = wf + (z ? 512 * 2048 : 0);
        int o = j >> 11;
        int rem = j & 2047;
        int p = rem >> 9;
        int c = rem & 511;
        d[(o << 11) + (p << 9) + c] =
            __float2half_rn(src[(o << 11) + (c << 2) + p]);
    } else if (bid < 42112) {
        int gw = (bid - 41984) * 8 + (tid >> 5);
        int lane = tid & 31;
        int n = gw & 511, isV = gw >> 9;
        const float* W  = isV ? Wv : Wk;
        const float* gg = isV ? gv : gk;
        const float* be = isV ? bev : bek;
        const float* bb = isV ? bv : bk;
        float* so = isV ? sv : sk;
        float* to = isV ? tv : tk;
        float s = 0.f, t = 0.f;
#pragma unroll
        for (int i = 0; i < 16; i++) {
            int c = lane + i * 32;
            float w = W[n * 512 + c];
            s += w * gg[c];
            t += w * be[c];
        }
#pragma unroll
        for (int off = 16; off; off >>= 1) {
            s += __shfl_xor_sync(0xffffffffu, s, off);
            t += __shfl_xor_sync(0xffffffffu, t, off);
        }
        if (lane == 0) { so[n] = s; to[n] = t + bb[n]; }
    } else if (bid < 42144) {
        int i = (bid - 42112) * 256 + tid;
        ((float4*)stats)[i] = make_float4(0.f, 0.f, 0.f, 0.f);
    } else {
#pragma unroll
        for (int k = 0; k < 4; k++) {
            int i = tid + k * 256;
            b2[i] = (i < 512) ? bsrk[i] : bsrv[i - 512];
        }
    }
}

// -------------------- HGEMM body (unchanged from round 16) -------------------
#define HG_STAGE_B (128 * 40 * 2)
#define HG_SMEM    (3 * 128 * 40 * 2 * 2)

__device__ __forceinline__ void hgemm_body(
    const __half* __restrict__ A, int lda,
    const __half* __restrict__ B,
    const float* __restrict__ bias, void* __restrict__ Cv, int ldc,
    int K, float alpha, int fp32_out, int im2col, int m0, int n0,
    int mode, float* __restrict__ stats,
    const float* __restrict__ svec, const float* __restrict__ tvec)
{
    extern __shared__ __half smx[];
    __half* AsB = smx;
    __half* BsB = smx + 3 * 128 * 40;
    const int tid = threadIdx.x, lane = tid & 31, wid = tid >> 5;
    const int g = lane >> 2, t4 = lane & 3;
    const int lr = lane & 7, lq = (lane >> 3) & 1, lh = lane >> 4;
    const int wm = (wid & 3) * 32, wn = (wid >> 2) * 64;
    const int row = tid >> 1, ch = (tid & 1) * 16;

    const __half* Apg;
    int n00 = 0;
    if (im2col) {
        int gr = m0 + row;
        int b_ = gr >> 10, m_ = gr & 1023;
        n00 = ((m_ >> 5) << 7) + ((m_ & 31) << 1);
        Apg = A + ((size_t)(b_ << 12)) * 512 + ch;
    } else {
        Apg = A + (size_t)(m0 + row) * lda + ch;
    }
    const __half* Bpg = B + (size_t)(n0 + row) * K + ch;

    const uint32_t asB = smem_u32(AsB);
    const uint32_t bsB = smem_u32(BsB);
    const uint32_t aSt = asB + (uint32_t)(row * 40 + ch) * 2;
    const uint32_t bSt = bsB + (uint32_t)(row * 40 + ch) * 2;
    const int rowA = wm + lr + lq * 8, colA = lh * 8;
    const int rowB = wn + lr + lh * 8, colB = lq * 8;

    float acc[2][8][4];
#pragma unroll
    for (int im = 0; im < 2; im++)
#pragma unroll
        for (int jn = 0; jn < 8; jn++)
#pragma unroll
            for (int e = 0; e < 4; e++) acc[im][jn][e] = 0.f;

    const int niter = K >> 5;
    auto issue = [&](int st, int kt) {
        const __half* Ap;
        if (im2col) {
            int p = kt >> 4;
            int n = n00 + ((p >> 1) << 6) + (p & 1);
            Ap = Apg + (size_t)n * 512 + ((kt & 15) << 5);
        } else {
            Ap = Apg + kt * 32;
        }
        const __half* Bp = Bpg + kt * 32;
        uint32_t ao = aSt + st * HG_STAGE_B;
        uint32_t bo = bSt + st * HG_STAGE_B;
        cpa16(ao,      Ap);
        cpa16(ao + 16, Ap + 8);
        cpa16(bo,      Bp);
        cpa16(bo + 16, Bp + 8);
        CP_COMMIT();
    };
    issue(0, 0);
    issue(1, 1);

    for (int it = 0; it < niter; it++) {
        CP_WAIT(1);
        __syncthreads();
        if (it + 2 < niter) issue((it + 2) % 3, it + 2);
        else CP_COMMIT();
        const int s = it % 3;
        const uint32_t aS = asB + (uint32_t)(s * HG_STAGE_B);
        const uint32_t bS = bsB + (uint32_t)(s * HG_STAGE_B);
#pragma unroll
        for (int kk = 0; kk < 32; kk += 16) {
            uint32_t a0[4], a1[4];
            ldsm4(a0, aS + (uint32_t)((rowA)      * 40 + kk + colA) * 2);
            ldsm4(a1, aS + (uint32_t)((rowA + 16) * 40 + kk + colA) * 2);
#pragma unroll
            for (int p = 0; p < 4; p++) {
                uint32_t bf[4];
                ldsm4(bf, bS + (uint32_t)((rowB + p * 16) * 40 + kk + colB) * 2);
                mma16(acc[0][2 * p],     a0, bf[0], bf[1]);
                mma16(acc[0][2 * p + 1], a0, bf[2], bf[3]);
                mma16(acc[1][2 * p],     a1, bf[0], bf[1]);
                mma16(acc[1][2 * p + 1], a1, bf[2], bf[3]);
            }
        }
    }

    if (mode == 2) {
#pragma unroll
        for (int im = 0; im < 2; im++) {
            int rA = m0 + wm + im * 16 + g;
            float2 stA = *(const float2*)&stats[rA * 2];
            float muA = stA.x * (1.f / 512.f);
            float ivA = rsqrtf(stA.y * (1.f / 512.f) - muA * muA + 1e-5f);
            float2 stB = *(const float2*)&stats[(rA + 8) * 2];
            float muB = stB.x * (1.f / 512.f);
            float ivB = rsqrtf(stB.y * (1.f / 512.f) - muB * muB + 1e-5f);
#pragma unroll
            for (int jn = 0; jn < 8; jn++) {
                int nc = n0 + wn + jn * 8 + 2 * t4;
                float2 sv2 = *(const float2*)&svec[nc];
                float2 tv2 = *(const float2*)&tvec[nc];
                size_t r0 = (size_t)rA * ldc + nc;
                float w00 = ivA * (acc[im][jn][0] - muA * sv2.x) + tv2.x;
                float w01 = ivA * (acc[im][jn][1] - muA * sv2.y) + tv2.y;
                float w10 = ivB * (acc[im][jn][2] - muB * sv2.x) + tv2.x;
                float w11 = ivB * (acc[im][jn][3] - muB * sv2.y) + tv2.y;
                __half* C = (__half*)Cv;
                *(uint32_t*)&C[r0]                   = h2(w00, w01);
                *(uint32_t*)&C[r0 + (size_t)8 * ldc] = h2(w10, w11);
            }
        }
    } else {
#pragma unroll
        for (int im = 0; im < 2; im++) {
            float s0 = 0.f, q0 = 0.f, s1 = 0.f, q1 = 0.f;
#pragma unroll
            for (int jn = 0; jn < 8; jn++) {
                int nc = n0 + wn + jn * 8 + 2 * t4;
                float2 bv = *(const float2*)(bias + nc);
                size_t r0 = (size_t)(m0 + wm + im * 16 + g) * ldc + nc;
                float w00 = (acc[im][jn][0] + bv.x) * alpha;
                float w01 = (acc[im][jn][1] + bv.y) * alpha;
                float w10 = (acc[im][jn][2] + bv.x) * alpha;
                float w11 = (acc[im][jn][3] + bv.y) * alpha;
                if (fp32_out) {
                    float* C = (float*)Cv;
                    *(float2*)&C[r0]                   = make_float2(w00, w01);
                    *(float2*)&C[r0 + (size_t)8 * ldc] = make_float2(w10, w11);
                } else {
                    __half* C = (__half*)Cv;
                    *(uint32_t*)&C[r0]                   = h2(w00, w01);
                    *(uint32_t*)&C[r0 + (size_t)8 * ldc] = h2(w10, w11);
                }
                if (mode == 1) {
                    s0 += w00 + w01; q0 += w00 * w00 + w01 * w01;
                    s1 += w10 + w11; q1 += w10 * w10 + w11 * w11;
                }
            }
            if (mode == 1) {
                s0 += __shfl_xor_sync(0xffffffffu, s0, 1);
                s0 += __shfl_xor_sync(0xffffffffu, s0, 2);
                q0 += __shfl_xor_sync(0xffffffffu, q0, 1);
                q0 += __shfl_xor_sync(0xffffffffu, q0, 2);
                s1 += __shfl_xor_sync(0xffffffffu, s1, 1);
                s1 += __shfl_xor_sync(0xffffffffu, s1, 2);
                q1 += __shfl_xor_sync(0xffffffffu, q1, 1);
                q1 += __shfl_xor_sync(0xffffffffu, q1, 2);
                if (t4 == 0) {
                    float* st = stats + (n0 >> 9) * 8192 * 2;
                    int rA = m0 + wm + im * 16 + g;
                    atomicAdd(&st[rA * 2],           s0);
                    atomicAdd(&st[rA * 2 + 1],       q0);
                    atomicAdd(&st[(rA + 8) * 2],     s1);
                    atomicAdd(&st[(rA + 8) * 2 + 1], q1);
                }
            }
        }
    }
}

__global__ __launch_bounds__(256, 2) void hgemm_convq(
    const __half* __restrict__ ctxh, const __half* __restrict__ wf,
    const float* __restrict__ b2, __half* __restrict__ srkv,
    float* __restrict__ stats,
    const __half* __restrict__ xh, const __half* __restrict__ wqh,
    const float* __restrict__ bq, __half* __restrict__ qh)
{
    int bid = blockIdx.x;
    if (bid < 512) {
        hgemm_body(ctxh, 0, wf, b2, srkv, 1024, 2048, 1.f, 0, 1,
                   (bid >> 3) * 128, (bid & 7) * 128, 1, stats,
                   nullptr, nullptr);
    } else {
        int q = bid - 512;
        hgemm_body(xh, 512, wqh, bq, qh, 512, 512,
                   0.125f * 1.44269504f, 0, 0,
                   (q >> 2) * 128, (q & 3) * 128, 0, nullptr,
                   nullptr, nullptr);
    }
}

__global__ __launch_bounds__(256, 2) void hgemm_kv(
    const __half* __restrict__ srkv,
    const __half* __restrict__ wkh, __half* __restrict__ kh,
    const __half* __restrict__ wvh, __half* __restrict__ vh,
    float* __restrict__ stats,
    const float* __restrict__ sk, const float* __restrict__ tk,
    const float* __restrict__ sv, const float* __restrict__ tv)
{
    if (blockIdx.z == 0)
        hgemm_body(srkv, 1024, wkh, tk, kh, 512, 512, 1.f, 0, 0,
                   blockIdx.y * 128, blockIdx.x * 128, 2, stats, sk, tk);
    else
        hgemm_body(srkv + 512, 1024, wvh, tv, vh, 512, 512, 1.f, 0, 0,
                   blockIdx.y * 128, blockIdx.x * 128, 2,
                   stats + 8192 * 2, sv, tv);
}

__global__ __launch_bounds__(256, 2) void hgemm_proj(
    const __half* __restrict__ atth, const __half* __restrict__ wph,
    const float* __restrict__ bp, float* __restrict__ out)
{
    hgemm_body(atth, 512, wph, bp, out, 512, 512, 1.f, 1, 0,
               blockIdx.y * 128, blockIdx.x * 128, 0, nullptr,
               nullptr, nullptr);
}

// -------------------- flash attention: 32-row warp tile, col-split warps -----
// 8 warps = 4 m-tiles (32 rows) x 2 col-halves (32 KV cols each). Each warp
// accumulates partial O/rowsums over its col-half (KV tiles are associative
// under fixed-max softmax); one smem merge at the end. B-fragments now feed
// 4 MMAs each -> LDSM per tile halves vs the 16-row layout.
#define AP 72
#define KV_STAGE_B (64 * AP * 2)
#define ATTN_SMEM ((128 * AP + 6 * 64 * AP) * 2)
#define ONES_H2 0x3C003C00u

__global__ __launch_bounds__(256, 1) void attn_mma(
    const __half* __restrict__ Q, const __half* __restrict__ Kg,
    const __half* __restrict__ Vg, __half* __restrict__ Og)
{
    extern __shared__ __half smx[];
    __half* Qs = smx;
    __half* Ks = smx + 128 * AP;
    __half* Vs = Ks + 3 * 64 * AP;
    float* red = (float*)Ks;    // 36 KB reduction buffer (reused after loop)

    const int bh = blockIdx.y;
    const int b = bh >> 3, h = bh & 7;
    const int n0 = blockIdx.x * 128;
    const int tid = threadIdx.x, lane = tid & 31, wid = tid >> 5;
    const int g = lane >> 2, t4 = lane & 3;
    const int lr = lane & 7, lq = (lane >> 3) & 1, lh = lane >> 4;
    const int mIdx = wid & 3, cHalf = wid >> 2;
    const int m0 = mIdx * 32;
    const int c0 = cHalf * 32;

    const uint32_t qsB = smem_u32(Qs);
    const uint32_t ksB = smem_u32(Ks);
    const uint32_t vsB = smem_u32(Vs);

    const int c = tid >> 2, dq = (tid & 3) * 16;
    const __half* kb0 = Kg + (size_t)(b << 10) * 512 + h * 64 + (size_t)c * 512 + dq;
    const __half* vb0 = Vg + (size_t)(b << 10) * 512 + h * 64 + (size_t)c * 512 + dq;
    const uint32_t kSt = ksB + (uint32_t)(c * AP + dq) * 2;
    const uint32_t vSt = vsB + (uint32_t)(c * AP + dq) * 2;

    auto issueKV = [&](int st, int t) {
        const __half* kp = kb0 + (size_t)t * 64 * 512;
        const __half* vp = vb0 + (size_t)t * 64 * 512;
        uint32_t ko = kSt + st * KV_STAGE_B;
        uint32_t vo = vSt + st * KV_STAGE_B;
        cpa16(ko,      kp);
        cpa16(ko + 16, kp + 8);
        cpa16(vo,      vp);
        cpa16(vo + 16, vp + 8);
        CP_COMMIT();
    };
    issueKV(0, 0);
    issueKV(1, 1);

    // stage Q
    {
        int qr = tid >> 1, dh = (tid & 1) * 32;
        const __half* qb = Q + (size_t)((b << 12) + n0 + qr) * 512 + h * 64 + dh;
#pragma unroll
        for (int i = 0; i < 4; i++)
            *(uint4*)&Qs[qr * AP + dh + i * 8] = *(const uint4*)(qb + i * 8);
    }
    __syncthreads();

    // Q fragments for 32 rows: qf[k4][mb*4..] (loaded once)
    uint32_t qf[4][8];
#pragma unroll
    for (int k4 = 0; k4 < 4; k4++) {
        ldsm4(&qf[k4][0], qsB + (uint32_t)((m0 + lr + lq * 8) * AP +
                                           k4 * 16 + lh * 8) * 2);
        ldsm4(&qf[k4][4], qsB + (uint32_t)((m0 + 16 + lr + lq * 8) * AP +
                                           k4 * 16 + lh * 8) * 2);
    }

    float oacc[2][8][4];
#pragma unroll
    for (int mb = 0; mb < 2; mb++)
#pragma unroll
        for (int nd = 0; nd < 8; nd++)
#pragma unroll
            for (int e = 0; e < 4; e++) oacc[mb][nd][e] = 0.f;
    float sumac[2][4] = {{0.f, 0.f, 0.f, 0.f}, {0.f, 0.f, 0.f, 0.f}};

    for (int t = 0; t < 16; t++) {
        CP_WAIT(1);
        __syncthreads();
        if (t + 2 < 16) issueKV((t + 2) % 3, t + 2);
        else CP_COMMIT();
        const uint32_t kS = ksB + (uint32_t)((t % 3) * KV_STAGE_B);
        const uint32_t vS = vsB + (uint32_t)((t % 3) * KV_STAGE_B);

        // S = Q K^T over this warp's 32-col half
        float sacc[2][4][4];
#pragma unroll
        for (int mb = 0; mb < 2; mb++)
#pragma unroll
            for (int jn = 0; jn < 4; jn++)
#pragma unroll
                for (int e = 0; e < 4; e++) sacc[mb][jn][e] = 0.f;
#pragma unroll
        for (int k4 = 0; k4 < 4; k4++) {
#pragma unroll
            for (int p = 0; p < 2; p++) {
                uint32_t bf[4];
                ldsm4(bf, kS + (uint32_t)((c0 + p * 16 + lr + lh * 8) * AP +
                                          k4 * 16 + lq * 8) * 2);
                mma16(sacc[0][2 * p],     &qf[k4][0], bf[0], bf[1]);
                mma16(sacc[0][2 * p + 1], &qf[k4][0], bf[2], bf[3]);
                mma16(sacc[1][2 * p],     &qf[k4][4], bf[0], bf[1]);
                mma16(sacc[1][2 * p + 1], &qf[k4][4], bf[2], bf[3]);
            }
        }

        // P = 2^S -> A fragments
        uint32_t pA[2][4], pB[2][4];
#pragma unroll
        for (int mb = 0; mb < 2; mb++)
#pragma unroll
            for (int jn = 0; jn < 4; jn++) {
                pA[mb][jn] = h2(ex2f(sacc[mb][jn][0]), ex2f(sacc[mb][jn][1]));
                pB[mb][jn] = h2(ex2f(sacc[mb][jn][2]), ex2f(sacc[mb][jn][3]));
            }

        // O += P V ; sums += P . 1   (V rows offset by this warp's c0)
#pragma unroll
        for (int kc = 0; kc < 2; kc++) {
            uint32_t af0[4] = { pA[0][2 * kc], pB[0][2 * kc],
                                pA[0][2 * kc + 1], pB[0][2 * kc + 1] };
            uint32_t af1[4] = { pA[1][2 * kc], pB[1][2 * kc],
                                pA[1][2 * kc + 1], pB[1][2 * kc + 1] };
            mma16(sumac[0], af0, ONES_H2, ONES_H2);
            mma16(sumac[1], af1, ONES_H2, ONES_H2);
#pragma unroll
            for (int p = 0; p < 4; p++) {
                uint32_t bf[4];
                ldsm4t(bf, vS + (uint32_t)((c0 + kc * 16 + lr + lq * 8) * AP +
                                           p * 16 + lh * 8) * 2);
                mma16(oacc[0][2 * p],     af0, bf[0], bf[1]);
                mma16(oacc[0][2 * p + 1], af0, bf[2], bf[3]);
                mma16(oacc[1][2 * p],     af1, bf[0], bf[1]);
                mma16(oacc[1][2 * p + 1], af1, bf[2], bf[3]);
            }
        }
    }

    // merge the two col-half partials through smem (KV buffers reusable now)
    __syncthreads();
    if (cHalf == 1) {
        float4* dst = (float4*)(red + (size_t)(mIdx * 32 + lane) * 72);
#pragma unroll
        for (int mb = 0; mb < 2; mb++)
#pragma unroll
            for (int nd = 0; nd < 8; nd++)
                dst[mb * 8 + nd] = make_float4(oacc[mb][nd][0], oacc[mb][nd][1],
                                               oacc[mb][nd][2], oacc[mb][nd][3]);
        dst[16] = make_float4(sumac[0][0], sumac[0][1], sumac[0][2], sumac[0][3]);
        dst[17] = make_float4(sumac[1][0], sumac[1][1], sumac[1][2], sumac[1][3]);
    }
    __syncthreads();
    if (cHalf == 0) {
        const float4* src = (const float4*)(red + (size_t)(mIdx * 32 + lane) * 72);
#pragma unroll
        for (int mb = 0; mb < 2; mb++)
#pragma unroll
            for (int nd = 0; nd < 8; nd++) {
                float4 v = src[mb * 8 + nd];
                oacc[mb][nd][0] += v.x; oacc[mb][nd][1] += v.y;
                oacc[mb][nd][2] += v.z; oacc[mb][nd][3] += v.w;
            }
        float4 s0 = src[16], s1 = src[17];
        sumac[0][0] += s0.x; sumac[0][2] += s0.z;
        sumac[1][0] += s1.x; sumac[1][2] += s1.z;

#pragma unroll
        for (int mb = 0; mb < 2; mb++) {
            float i0 = 1.f / sumac[mb][0], i1 = 1.f / sumac[mb][2];
            size_t r0 = (size_t)((b << 12) + n0 + m0 + mb * 16 + g) * 512 + h * 64;
            size_t r1 = r0 + (size_t)8 * 512;
#pragma unroll
            for (int nd = 0; nd < 8; nd++) {
                int col = nd * 8 + 2 * t4;
                *(uint32_t*)&Og[r0 + col] =
                    h2(oacc[mb][nd][0] * i0, oacc[mb][nd][1] * i0);
                *(uint32_t*)&Og[r1 + col] =
                    h2(oacc[mb][nd][2] * i1, oacc[mb][nd][3] * i1);
            }
        }
    }
}

// -------------------- launcher ----------------------------------------------
extern "C" void kernel_launch(void* const* d_in, const int* in_sizes, int n_in,
                              void* d_out, int out_size) {
    const float* x       = (const float*)d_in[0];
    const float* context = (const float*)d_in[1];
    const float* Wq   = (const float*)d_in[2];
    const float* bq   = (const float*)d_in[3];
    const float* Wk   = (const float*)d_in[4];
    const float* bk   = (const float*)d_in[5];
    const float* Wv   = (const float*)d_in[6];
    const float* bv   = (const float*)d_in[7];
    const float* Wp   = (const float*)d_in[8];
    const float* bp   = (const float*)d_in[9];
    const float* Wsrk = (const float*)d_in[10];
    const float* bsrk = (const float*)d_in[11];
    const float* Wsrv = (const float*)d_in[12];
    const float* bsrv = (const float*)d_in[13];
    const float* gk   = (const float*)d_in[14];
    const float* bek  = (const float*)d_in[15];
    const float* gv   = (const float*)d_in[16];
    const float* bev  = (const float*)d_in[17];

    __half *ctxh, *wf, *xh, *wqh, *wkh, *wvh, *wph, *srkv, *qh, *kh, *vh, *atth;
    float *b2, *stats, *sk, *tk, *sv, *tv;
    cudaGetSymbolAddress((void**)&ctxh, g_ctxh);
    cudaGetSymbolAddress((void**)&wf, g_wf_h);
    cudaGetSymbolAddress((void**)&b2, g_b2);
    cudaGetSymbolAddress((void**)&xh, g_xh);
    cudaGetSymbolAddress((void**)&wqh, g_wqh);
    cudaGetSymbolAddress((void**)&wkh, g_wkh);
    cudaGetSymbolAddress((void**)&wvh, g_wvh);
    cudaGetSymbolAddress((void**)&wph, g_wph);
    cudaGetSymbolAddress((void**)&srkv, g_srkv_h);
    cudaGetSymbolAddress((void**)&stats, g_stats);
    cudaGetSymbolAddress((void**)&sk, g_sk);
    cudaGetSymbolAddress((void**)&tk, g_tk);
    cudaGetSymbolAddress((void**)&sv, g_sv);
    cudaGetSymbolAddress((void**)&tv, g_tv);
    cudaGetSymbolAddress((void**)&qh, g_qh);
    cudaGetSymbolAddress((void**)&kh, g_kh);
    cudaGetSymbolAddress((void**)&vh, g_vh);
    cudaGetSymbolAddress((void**)&atth, g_atth);

    cudaFuncSetAttribute(hgemm_convq,
                         cudaFuncAttributeMaxDynamicSharedMemorySize, HG_SMEM);
    cudaFuncSetAttribute(hgemm_kv,
                         cudaFuncAttributeMaxDynamicSharedMemorySize, HG_SMEM);
    cudaFuncSetAttribute(hgemm_proj,
                         cudaFuncAttributeMaxDynamicSharedMemorySize, HG_SMEM);
    cudaFuncSetAttribute(attn_mma,
                         cudaFuncAttributeMaxDynamicSharedMemorySize, ATTN_SMEM);

    mega_prep<<<42145, 256>>>(x, xh, context, ctxh,
                              Wq, Wk, Wv, Wp, wqh, wkh, wvh, wph,
                              gk, gv, Wsrk, Wsrv, wf,
                              bek, bev, bk, bv, sk, tk, sv, tv,
                              bsrk, bsrv, b2, stats);
    hgemm_convq<<<1536, 256, HG_SMEM>>>(ctxh, wf, b2, srkv, stats,
                                        xh, wqh, bq, qh);
    dim3 gkv(4, 64, 2);
    hgemm_kv<<<gkv, 256, HG_SMEM>>>(srkv, wkh, kh, wvh, vh,
                                    stats, sk, tk, sv, tv);
    dim3 ga(32, 64);
    attn_mma<<<ga, 256, ATTN_SMEM>>>(qh, kh, vh, atth);
    dim3 g2(4, 256);
    hgemm_proj<<<g2, 256, HG_SMEM>>>(atth, wph, bp, (float*)d_out);
}